// round 1
// baseline (speedup 1.0000x reference)
#include <cuda_runtime.h>
#include <cuda_bf16.h>

#define NB 16
#define NE 2048
#define NP 16384
#define NL 5
#define ND 64

// Scratch: per-(b,e,l) dot products, 16*2048*5 floats = 640 KB
__device__ __align__(16) float g_dot[NB * NE * NL];
__device__ int g_is64;

// ---------------------------------------------------------------------------
// Kernel 0: detect whether edge_paths is int64 or int32.
// If int64: every odd 32-bit word is a sign-extension word (0 or -1).
// If int32: odd words are uniform in [-1, 2048) -> violation found quickly.
// ---------------------------------------------------------------------------
__global__ void detect_kernel(const int* __restrict__ pw) {
    __shared__ int bad;
    if (threadIdx.x == 0) bad = 0;
    __syncthreads();
    for (int i = threadIdx.x; i < 4096; i += blockDim.x) {
        int w = pw[2 * i + 1];
        if (w != 0 && w != -1) bad = 1;  // benign race: all writers store 1
    }
    __syncthreads();
    if (threadIdx.x == 0) g_is64 = bad ? 0 : 1;
}

// ---------------------------------------------------------------------------
// Kernel 1: dot[b,e,l] = sum_d emb[b,e,d] * ev[l,d]
// One warp per (b,e) row. float2 per lane, 5 butterfly reductions.
// ---------------------------------------------------------------------------
__global__ __launch_bounds__(256) void dot_kernel(
    const float* __restrict__ emb, const float* __restrict__ ev) {
    int row  = (blockIdx.x * blockDim.x + threadIdx.x) >> 5;  // (b*E + e)
    int lane = threadIdx.x & 31;
    if (row >= NB * NE) return;

    const float2* r2 = reinterpret_cast<const float2*>(emb + (size_t)row * ND);
    float2 v = r2[lane];

    const float2* ev2 = reinterpret_cast<const float2*>(ev);
    float res = 0.f;
    #pragma unroll
    for (int l = 0; l < NL; l++) {
        float2 e = ev2[l * (ND / 2) + lane];
        float s = v.x * e.x + v.y * e.y;
        #pragma unroll
        for (int off = 16; off > 0; off >>= 1)
            s += __shfl_xor_sync(0xffffffffu, s, off);
        // after butterfly, all lanes hold the sum; lane l keeps its copy
        if (lane == l) res = s;
    }
    if (lane < NL) g_dot[row * NL + lane] = res;
}

// ---------------------------------------------------------------------------
// Kernel 2: enc[b,p] = (sum_l valid ? dot[b, idx, l] : 0) / (count + 1e-9)
// grid = (NP / (512*PPT), NB). 40 KB per-batch dot table staged in shared.
// ---------------------------------------------------------------------------
#define ENC_THREADS 512
#define PPT 2

__global__ __launch_bounds__(ENC_THREADS) void enc_kernel(
    const void* __restrict__ paths, float* __restrict__ out) {
    __shared__ float tab[NE * NL];  // 40 KB

    int b = blockIdx.y;
    // stage the batch's dot table (float4-vectorized, 16B-aligned)
    const float4* src = reinterpret_cast<const float4*>(g_dot + (size_t)b * NE * NL);
    float4* dst = reinterpret_cast<float4*>(tab);
    for (int i = threadIdx.x; i < (NE * NL) / 4; i += ENC_THREADS)
        dst[i] = src[i];
    __syncthreads();

    const bool is64 = (g_is64 != 0);
    const long long* p64 = reinterpret_cast<const long long*>(paths);
    const int*       p32 = reinterpret_cast<const int*>(paths);
    const size_t base = (size_t)b * NP * NL;

    #pragma unroll
    for (int it = 0; it < PPT; it++) {
        int p = blockIdx.x * (ENC_THREADS * PPT) + it * ENC_THREADS + threadIdx.x;
        size_t off = base + (size_t)p * NL;
        float acc = 0.f;
        int cnt = 0;
        if (is64) {
            #pragma unroll
            for (int l = 0; l < NL; l++) {
                long long idx = __ldg(p64 + off + l);
                if (idx >= 0) { acc += tab[(int)idx * NL + l]; cnt++; }
            }
        } else {
            #pragma unroll
            for (int l = 0; l < NL; l++) {
                int idx = __ldg(p32 + off + l);
                if (idx >= 0) { acc += tab[idx * NL + l]; cnt++; }
            }
        }
        out[(size_t)b * NP + p] = acc / ((float)cnt + 1e-9f);
    }
}

// ---------------------------------------------------------------------------
extern "C" void kernel_launch(void* const* d_in, const int* in_sizes, int n_in,
                              void* d_out, int out_size) {
    const float* emb   = (const float*)d_in[0];  // (B, E, D) float32
    const void*  paths = d_in[1];                // (B, P, L) int64 or int32
    const float* ev    = (const float*)d_in[2];  // (L, D) float32
    float* out = (float*)d_out;                  // (B, P) float32

    detect_kernel<<<1, 256>>>((const int*)paths);

    int rows = NB * NE;                    // 32768 warps, 8 warps/block
    dot_kernel<<<rows / 8, 256>>>(emb, ev);

    dim3 grid(NP / (ENC_THREADS * PPT), NB);  // (16, 16)
    enc_kernel<<<grid, ENC_THREADS>>>(paths, out);
}

// round 3
// speedup vs baseline: 1.1123x; 1.1123x over previous
#include <cuda_runtime.h>
#include <cuda_bf16.h>

#define NB 16
#define NE 2048
#define NP 16384
#define NL 5
#define ND 64

// Scratch: per-(b,e,l) dot products, 16*2048*5 floats = 640 KB
__device__ __align__(16) float g_dot[NB * NE * NL];
__device__ int g_is64;

// ---------------------------------------------------------------------------
// Kernel 1: dot[b,e,l] = sum_d emb[b,e,d] * ev[l,d]
// One warp per (b,e) row. float2 per lane, 5 butterfly reductions.
// Block 0 additionally sniffs the paths dtype (int64 -> odd words are 0/-1
// sign-extensions; int32 -> statistically impossible over 4096 samples) and
// publishes g_is64 before this kernel retires (stream order protects enc).
// ---------------------------------------------------------------------------
__global__ __launch_bounds__(256) void dot_kernel(
    const float* __restrict__ emb, const float* __restrict__ ev,
    const int* __restrict__ pathw) {

    if (blockIdx.x == 0) {
        // dtype sniff: 4096 odd 32-bit words, 16 per thread
        int bad = 0;
        #pragma unroll 4
        for (int i = threadIdx.x; i < 4096; i += 256) {
            int w = __ldg(pathw + 2 * i + 1);
            bad |= (w != 0 && w != -1);
        }
        // any-thread reduction via ballot across the block
        bad = __syncthreads_or(bad);
        if (threadIdx.x == 0) g_is64 = bad ? 0 : 1;
    }

    int row  = (blockIdx.x * blockDim.x + threadIdx.x) >> 5;  // (b*E + e)
    int lane = threadIdx.x & 31;
    if (row >= NB * NE) return;

    const float2* r2 = reinterpret_cast<const float2*>(emb + (size_t)row * ND);
    float2 v = r2[lane];

    const float2* ev2 = reinterpret_cast<const float2*>(ev);
    float res = 0.f;
    #pragma unroll
    for (int l = 0; l < NL; l++) {
        float2 e = ev2[l * (ND / 2) + lane];
        float s = v.x * e.x + v.y * e.y;
        #pragma unroll
        for (int off = 16; off > 0; off >>= 1)
            s += __shfl_xor_sync(0xffffffffu, s, off);
        if (lane == l) res = s;
    }
    if (lane < NL) g_dot[row * NL + lane] = res;
}

// ---------------------------------------------------------------------------
// Kernel 2: enc[b,p] = (sum_l valid ? dot[b, idx, l] : 0) * recip[count]
// grid = (NP / (512*PPT), NB). 40 KB per-batch dot table staged in shared.
// ---------------------------------------------------------------------------
#define ENC_THREADS 512
#define PPT 2

__constant__ float c_recip[8] = {
    0.f,                       // cnt=0: acc is 0, product 0 matches 0/(0+eps)
    1.0f / (1.0f + 1e-9f),
    1.0f / (2.0f + 1e-9f),
    1.0f / (3.0f + 1e-9f),
    1.0f / (4.0f + 1e-9f),
    1.0f / (5.0f + 1e-9f),
    0.f, 0.f
};

__global__ __launch_bounds__(ENC_THREADS) void enc_kernel(
    const void* __restrict__ paths, float* __restrict__ out) {
    __shared__ float tab[NE * NL];  // 40 KB

    int b = blockIdx.y;
    // stage the batch's dot table (float4-vectorized, 16B-aligned)
    const float4* src = reinterpret_cast<const float4*>(g_dot + (size_t)b * NE * NL);
    float4* dst = reinterpret_cast<float4*>(tab);
    #pragma unroll
    for (int i = threadIdx.x; i < (NE * NL) / 4; i += ENC_THREADS)
        dst[i] = src[i];
    __syncthreads();

    const bool is64 = (g_is64 != 0);
    const long long* p64 = reinterpret_cast<const long long*>(paths);
    const int*       p32 = reinterpret_cast<const int*>(paths);
    const size_t base = (size_t)b * NP * NL;

    #pragma unroll
    for (int it = 0; it < PPT; it++) {
        int p = blockIdx.x * (ENC_THREADS * PPT) + it * ENC_THREADS + threadIdx.x;
        size_t off = base + (size_t)p * NL;
        float acc = 0.f;
        int cnt = 0;
        if (is64) {
            #pragma unroll
            for (int l = 0; l < NL; l++) {
                long long idx = __ldg(p64 + off + l);
                if (idx >= 0) { acc += tab[(int)idx * NL + l]; cnt++; }
            }
        } else {
            #pragma unroll
            for (int l = 0; l < NL; l++) {
                int idx = __ldg(p32 + off + l);
                if (idx >= 0) { acc += tab[idx * NL + l]; cnt++; }
            }
        }
        out[(size_t)b * NP + p] = acc * c_recip[cnt];
    }
}

// ---------------------------------------------------------------------------
extern "C" void kernel_launch(void* const* d_in, const int* in_sizes, int n_in,
                              void* d_out, int out_size) {
    const float* emb   = (const float*)d_in[0];  // (B, E, D) float32
    const void*  paths = d_in[1];                // (B, P, L) int64 or int32
    const float* ev    = (const float*)d_in[2];  // (L, D) float32
    float* out = (float*)d_out;                  // (B, P) float32

    int rows = NB * NE;                    // 32768 warps, 8 warps/block
    dot_kernel<<<rows / 8, 256>>>(emb, ev, (const int*)paths);

    dim3 grid(NP / (ENC_THREADS * PPT), NB);  // (16, 16)
    enc_kernel<<<grid, ENC_THREADS>>>(paths, out);
}

// round 4
// speedup vs baseline: 1.5970x; 1.4358x over previous
#include <cuda_runtime.h>
#include <cuda_bf16.h>

#define NB 16
#define NE 2048
#define NP 16384
#define NL 5
#define ND 64

// Scratch: per-(b,e,l) dot products, 16*2048*5 floats = 640 KB
__device__ __align__(16) float g_dot[NB * NE * NL];
__device__ int g_is64;

// ---------------------------------------------------------------------------
// Kernel 1: dot[b,e,l] = sum_d emb[b,e,d] * ev[l,d]
// 8 lanes per row (each lane: 8 floats via 2x float4, fully coalesced:
// lanes 0..7 cover bytes [0,128) of row r, etc). 4 rows per warp.
// Per l: 8 FMAs then 3-step butterfly over the 8-lane group.
// Block 0 also sniffs the paths dtype (int64 -> odd 32-bit words are 0/-1).
// ---------------------------------------------------------------------------
__global__ __launch_bounds__(256) void dot_kernel(
    const float* __restrict__ emb, const float* __restrict__ ev,
    const int* __restrict__ pathw) {

    if (blockIdx.x == 0) {
        int bad = 0;
        #pragma unroll 4
        for (int i = threadIdx.x; i < 4096; i += 256) {
            int w = __ldg(pathw + 2 * i + 1);
            bad |= (w != 0 && w != -1);
        }
        bad = __syncthreads_or(bad);
        if (threadIdx.x == 0) g_is64 = bad ? 0 : 1;
    }

    int warp = threadIdx.x >> 5;
    int lane = threadIdx.x & 31;
    int grp  = lane >> 3;          // 4 rows per warp
    int sub  = lane & 7;           // 8 lanes per row
    int row  = blockIdx.x * 32 + warp * 4 + grp;   // (b*E + e), grid covers all

    const float4* rp = reinterpret_cast<const float4*>(emb) + (size_t)row * (ND / 4);
    float4 v0 = rp[sub];           // bytes [sub*16, sub*16+16)     -> d in [sub*4, sub*4+4)
    float4 v1 = rp[sub + 8];       // bytes [128+sub*16, ...)       -> d in [32+sub*4, ...)

    const float4* ev4 = reinterpret_cast<const float4*>(ev);
    float res = 0.f;
    #pragma unroll
    for (int l = 0; l < NL; l++) {
        float4 e0 = ev4[l * (ND / 4) + sub];
        float4 e1 = ev4[l * (ND / 4) + 8 + sub];
        float s = v0.x * e0.x + v0.y * e0.y + v0.z * e0.z + v0.w * e0.w
                + v1.x * e1.x + v1.y * e1.y + v1.z * e1.z + v1.w * e1.w;
        s += __shfl_xor_sync(0xffffffffu, s, 1);
        s += __shfl_xor_sync(0xffffffffu, s, 2);
        s += __shfl_xor_sync(0xffffffffu, s, 4);
        if (sub == l) res = s;     // lane `l` of each 8-lane group keeps sum_l
    }
    if (sub < NL) g_dot[row * NL + sub] = res;
}

// ---------------------------------------------------------------------------
// Kernel 2: enc[b,p] = (sum_l valid ? dot[b, idx, l] : 0) * recip[count]
// 512 threads, 1024 p per block -> grid (16, 16), single wave (2 blocks/SM).
// Dynamic smem: 40KB dot table + 40KB staged path chunk (int4-coalesced).
// Gather uses only the low 32-bit word of each path index (valid for both
// int32 and int64: low word of -1 is -1, valid ids < 2^31).
// ---------------------------------------------------------------------------
#define ETH 512
#define EPPT 2
#define PBLK (ETH * EPPT)                 // 1024 paths per block
#define ENC_SMEM (NE * NL * 4 + PBLK * NL * 8)   // 40960 + 40960 = 81920 B

__constant__ float c_recip[8] = {
    0.f,                       // cnt=0: acc is 0; 0 matches 0/(0+eps)
    1.0f / (1.0f + 1e-9f),
    1.0f / (2.0f + 1e-9f),
    1.0f / (3.0f + 1e-9f),
    1.0f / (4.0f + 1e-9f),
    1.0f / (5.0f + 1e-9f),
    0.f, 0.f
};

__global__ __launch_bounds__(ETH) void enc_kernel(
    const void* __restrict__ paths, float* __restrict__ out) {
    extern __shared__ unsigned char smem[];
    float* tab = reinterpret_cast<float*>(smem);          // NE*NL floats
    unsigned char* pstage = smem + NE * NL * 4;           // staged path chunk

    const int b  = blockIdx.y;
    const int p0 = blockIdx.x * PBLK;
    const bool is64 = (g_is64 != 0);

    // stage the batch's dot table (float4-vectorized)
    {
        const float4* src = reinterpret_cast<const float4*>(g_dot + (size_t)b * NE * NL);
        float4* dst = reinterpret_cast<float4*>(tab);
        #pragma unroll
        for (int i = threadIdx.x; i < (NE * NL) / 4; i += ETH)
            dst[i] = src[i];
    }
    // stage this block's path chunk, fully coalesced int4
    {
        const size_t elem = is64 ? 8 : 4;
        const int4* psrc = reinterpret_cast<const int4*>(
            (const unsigned char*)paths + ((size_t)b * NP + p0) * NL * elem);
        int4* pdst = reinterpret_cast<int4*>(pstage);
        const int n16 = (int)((PBLK * NL * elem) >> 4);   // 2560 (i64) / 1280 (i32)
        for (int i = threadIdx.x; i < n16; i += ETH)
            pdst[i] = psrc[i];
    }
    __syncthreads();

    const int* sp = reinterpret_cast<const int*>(pstage);
    const int stride = is64 ? 2 : 1;   // read low word only

    #pragma unroll
    for (int it = 0; it < EPPT; it++) {
        int lp = it * ETH + threadIdx.x;        // local p in [0, PBLK)
        const int* q = sp + lp * NL * stride;
        float acc = 0.f;
        int cnt = 0;
        #pragma unroll
        for (int l = 0; l < NL; l++) {
            int idx = q[l * stride];
            if (idx >= 0) { acc += tab[idx * NL + l]; cnt++; }
        }
        out[(size_t)b * NP + p0 + lp] = acc * c_recip[cnt];
    }
}

// ---------------------------------------------------------------------------
extern "C" void kernel_launch(void* const* d_in, const int* in_sizes, int n_in,
                              void* d_out, int out_size) {
    const float* emb   = (const float*)d_in[0];  // (B, E, D) float32
    const void*  paths = d_in[1];                // (B, P, L) int64 or int32
    const float* ev    = (const float*)d_in[2];  // (L, D) float32
    float* out = (float*)d_out;                  // (B, P) float32

    // 32768 rows, 32 rows/block
    dot_kernel<<<NB * NE / 32, 256>>>(emb, ev, (const int*)paths);

    cudaFuncSetAttribute(enc_kernel, cudaFuncAttributeMaxDynamicSharedMemorySize,
                         ENC_SMEM);
    dim3 grid(NP / PBLK, NB);                 // (16, 16)
    enc_kernel<<<grid, ETH, ENC_SMEM>>>(paths, out);
}